// round 17
// baseline (speedup 1.0000x reference)
#include <cuda_runtime.h>
#include <cuda_bf16.h>
#include <cstdint>
#include <cstddef>

#define BATCH 16
#define NPTS  8192
#define NSAMP 1024
#define NGRP  32
#define FDIM  64
#define NITEM (BATCH * NSAMP)            // 16384 single-centroid work items

// ---------------- device scratch ----------------
__device__ float4 g_p4[BATCH][NPTS];     // x,y,z,sumsq
__device__ int    g_fps[BATCH][NSAMP];
__device__ int    g_grp[BATCH][NSAMP][NGRP];
__device__ int    g_prog[BATCH];
__device__ int    g_qhead;

// B fragments pre-packed per mma lane: uint4 = {b0_hi, b1_hi, b0_lo, b1_lo}
__device__ uint4 g_W1f[8 * 5 * 32];
__device__ uint4 g_W2f[16 * 4 * 32];
__device__ uint4 g_W3f[32 * 8 * 32];

static __device__ __forceinline__ unsigned pkbf(float a, float b) {
    __nv_bfloat16 ha = __float2bfloat16(a), hb = __float2bfloat16(b);
    return (unsigned)__bfloat16_as_ushort(ha) |
           ((unsigned)__bfloat16_as_ushort(hb) << 16);
}
static __device__ __forceinline__ uint4 packfrag(const float* W, int K, int ldw,
                                                 int nbg, int kb, int l) {
    int n = nbg * 8 + (l >> 2);
    int k = kb * 16 + 2 * (l & 3);
    float w0 = (k     < K) ? __ldg(W + k * ldw + n)       : 0.f;
    float w1 = (k + 1 < K) ? __ldg(W + (k + 1) * ldw + n) : 0.f;
    float w8 = (k + 8 < K) ? __ldg(W + (k + 8) * ldw + n) : 0.f;
    float w9 = (k + 9 < K) ? __ldg(W + (k + 9) * ldw + n) : 0.f;
    float r0 = w0 - __bfloat162float(__float2bfloat16(w0));
    float r1 = w1 - __bfloat162float(__float2bfloat16(w1));
    float r8 = w8 - __bfloat162float(__float2bfloat16(w8));
    float r9 = w9 - __bfloat162float(__float2bfloat16(w9));
    uint4 o;
    o.x = pkbf(w0, w1); o.y = pkbf(w8, w9);
    o.z = pkbf(r0, r1); o.w = pkbf(r8, r9);
    return o;
}

__global__ void init_kernel(const float* __restrict__ W1,
                            const float* __restrict__ W2,
                            const float* __restrict__ W3) {
    int nth = gridDim.x * blockDim.x;
    int i = blockIdx.x * blockDim.x + threadIdx.x;
    if (i < BATCH) g_prog[i] = 0;
    if (i == BATCH) g_qhead = 0;
    for (int idx = i; idx < 8 * 5 * 32; idx += nth) {
        int l = idx & 31, kb = (idx >> 5) % 5, nbg = idx / 160;
        g_W1f[idx] = packfrag(W1, 67, 64, nbg, kb, l);
    }
    for (int idx = i; idx < 16 * 4 * 32; idx += nth) {
        int l = idx & 31, kb = (idx >> 5) & 3, nbg = idx >> 7;
        g_W2f[idx] = packfrag(W2, 64, 128, nbg, kb, l);
    }
    for (int idx = i; idx < 32 * 8 * 32; idx += nth) {
        int l = idx & 31, kb = (idx >> 5) & 7, nbg = idx >> 8;
        g_W3f[idx] = packfrag(W3, 128, 256, nbg, kb, l);
    }
}

// =====================================================================
// SMEM (dynamic, 139264 B):
//  consumer: pair p (0..7): A hi @ p*8704 ([32][136] bf16), A lo @ +69632
//  fps: sx/sy/sz[8192] f32, sidx[8192] i32, sspos[1024], cnt[512], base[512]
// =====================================================================
#define LDA       136
#define ALO_GAP   69632
#define PAIR_A    8704
#define SMEM_TOT  139264

static __device__ __forceinline__ uint32_t smem_u32(const void* p) {
    uint32_t a;
    asm("{ .reg .u64 t; cvta.to.shared.u64 t, %1; cvt.u32.u64 %0, t; }"
        : "=r"(a) : "l"(p));
    return a;
}
static __device__ __forceinline__ void ldm_x4(uint32_t* r, uint32_t addr) {
    asm volatile("ldmatrix.sync.aligned.m8n8.x4.shared.b16 {%0,%1,%2,%3}, [%4];"
                 : "=r"(r[0]), "=r"(r[1]), "=r"(r[2]), "=r"(r[3]) : "r"(addr));
}
static __device__ __forceinline__ void mma_bf16(float* c, const uint32_t* a,
                                                uint32_t b0, uint32_t b1) {
    asm volatile(
        "mma.sync.aligned.m16n8k16.row.col.f32.bf16.bf16.f32 "
        "{%0,%1,%2,%3}, {%4,%5,%6,%7}, {%8,%9}, {%0,%1,%2,%3};"
        : "+f"(c[0]), "+f"(c[1]), "+f"(c[2]), "+f"(c[3])
        : "r"(a[0]), "r"(a[1]), "r"(a[2]), "r"(a[3]), "r"(b0), "r"(b1));
}

// fast bf16x2 pack: lo-half = a, hi-half = b (cvt.rn == scalar __float2bfloat16)
static __device__ __forceinline__ unsigned pack2(float a, float b) {
    unsigned r;
    asm("cvt.rn.bf16x2.f32 %0, %1, %2;" : "=r"(r) : "f"(b), "f"(a));
    return r;
}
// bit-exact fast split: hi = pack(a,b); lo = pack(a-hi.a, b-hi.b)
static __device__ __forceinline__ void split2(float a, float b,
                                              unsigned& hi, unsigned& lo) {
    hi = pack2(a, b);
    float ah = __uint_as_float(hi << 16);
    float bh = __uint_as_float(hi & 0xffff0000u);
    lo = pack2(a - ah, b - bh);
}
static __device__ __forceinline__ void storeA(char* aBase, int row, int col,
                                              float a, float b) {
    unsigned h, l;
    split2(a, b, h, l);
    int off = (row * LDA + col) * 2;
    *(unsigned*)(aBase + off) = h;
    *(unsigned*)(aBase + ALO_GAP + off) = l;
}

// warp GEMM over the pair's 32 rows; B fragments from packed global arrays.
// NBLK==4: next-k software prefetch of B; NBLK==8: LDG-first per k-step.
template <int NBLK, int KSTEPS>
static __device__ __forceinline__ void warp_gemm_ldg(
    uint32_t aB, const uint4* __restrict__ Wf, int nbgBase, int KB,
    float (&acc)[2][NBLK][4])
{
    int lane = threadIdx.x & 31;
#pragma unroll
    for (int m = 0; m < 2; m++)
#pragma unroll
        for (int nb = 0; nb < NBLK; nb++)
#pragma unroll
            for (int i = 0; i < 4; i++) acc[m][nb][i] = 0.f;

    int arow = lane & 15;
    int acolo = (lane >> 4) << 3;
    const uint4* base = Wf + (size_t)nbgBase * KB * 32 + lane;

    if constexpr (NBLK == 4) {
        uint4 f[4], fn[4];
#pragma unroll
        for (int q = 0; q < 4; q++) f[q] = __ldg(base + (size_t)q * KB * 32);
#pragma unroll
        for (int k = 0; k < KSTEPS; k++) {
            int k0 = k << 4;
            uint32_t ah[2][4], al[2][4];
#pragma unroll
            for (int m = 0; m < 2; m++) {
                uint32_t ao = (uint32_t)(((m * 16 + arow) * LDA + k0 + acolo) * 2);
                ldm_x4(ah[m], aB + ao);
                ldm_x4(al[m], aB + ALO_GAP + ao);
            }
            if (k + 1 < KSTEPS) {
#pragma unroll
                for (int q = 0; q < 4; q++)
                    fn[q] = __ldg(base + ((size_t)q * KB + k + 1) * 32);
            }
#pragma unroll
            for (int q = 0; q < 4; q++) {
#pragma unroll
                for (int m = 0; m < 2; m++) {
                    mma_bf16(acc[m][q], ah[m], f[q].x, f[q].y);
                    mma_bf16(acc[m][q], ah[m], f[q].z, f[q].w);
                    mma_bf16(acc[m][q], al[m], f[q].x, f[q].y);
                }
            }
            if (k + 1 < KSTEPS) {
#pragma unroll
                for (int q = 0; q < 4; q++) f[q] = fn[q];
            }
        }
    } else {
#pragma unroll
        for (int k = 0; k < KSTEPS; k++) {
            int k0 = k << 4;
            uint4 f[NBLK];
#pragma unroll
            for (int q = 0; q < NBLK; q++)
                f[q] = __ldg(base + ((size_t)q * KB + k) * 32);
            uint32_t ah[2][4], al[2][4];
#pragma unroll
            for (int m = 0; m < 2; m++) {
                uint32_t ao = (uint32_t)(((m * 16 + arow) * LDA + k0 + acolo) * 2);
                ldm_x4(ah[m], aB + ao);
                ldm_x4(al[m], aB + ALO_GAP + ao);
            }
#pragma unroll
            for (int q = 0; q < NBLK; q++) {
#pragma unroll
                for (int m = 0; m < 2; m++) {
                    mma_bf16(acc[m][q], ah[m], f[q].x, f[q].y);
                    mma_bf16(acc[m][q], ah[m], f[q].z, f[q].w);
                    mma_bf16(acc[m][q], al[m], f[q].x, f[q].y);
                }
            }
        }
    }
}

template <int NBLK>
static __device__ __forceinline__ void epi_store(char* aBase, int colBase,
                                                 const float* __restrict__ bias,
                                                 float (&acc)[2][NBLK][4]) {
    int lane = threadIdx.x & 31;
    int cq = (lane & 3) * 2;
    int rq = lane >> 2;
#pragma unroll
    for (int nb = 0; nb < NBLK; nb++) {
        int col = colBase + nb * 8 + cq;
        float b0 = __ldg(bias + col), b1 = __ldg(bias + col + 1);
#pragma unroll
        for (int m = 0; m < 2; m++) {
            int row = m * 16 + rq;
            float v0 = fmaxf(acc[m][nb][0] + b0, 0.f);
            float v1 = fmaxf(acc[m][nb][1] + b1, 0.f);
            float v2 = fmaxf(acc[m][nb][2] + b0, 0.f);
            float v3 = fmaxf(acc[m][nb][3] + b1, 0.f);
            storeA(aBase, row, col, v0, v1);
            storeA(aBase, row + 8, col, v2, v3);
        }
    }
}

template <int NBLK>
static __device__ __forceinline__ void epi_max(int gColBase, const float* __restrict__ B3,
                                               float* __restrict__ out, size_t obase,
                                               float (&acc)[2][NBLK][4]) {
    int lane = threadIdx.x & 31;
    int cq = (lane & 3) * 2;
#pragma unroll
    for (int nb = 0; nb < NBLK; nb++) {
        int col = gColBase + nb * 8 + cq;
        float b0 = __ldg(B3 + col), b1 = __ldg(B3 + col + 1);
        float v0 = fmaxf(fmaxf(acc[0][nb][0], acc[0][nb][2]),
                         fmaxf(acc[1][nb][0], acc[1][nb][2])) + b0;
        float v1 = fmaxf(fmaxf(acc[0][nb][1], acc[0][nb][3]),
                         fmaxf(acc[1][nb][1], acc[1][nb][3])) + b1;
        v0 = fmaxf(v0, 0.f); v1 = fmaxf(v1, 0.f);
#pragma unroll
        for (int off = 4; off <= 16; off <<= 1) {
            v0 = fmaxf(v0, __shfl_xor_sync(0xffffffffu, v0, off));
            v1 = fmaxf(v1, __shfl_xor_sync(0xffffffffu, v1, off));
        }
        if (lane < 4) {
            out[obase + col] = v0;
            out[obase + col + 1] = v1;
        }
    }
}

static __device__ __forceinline__ unsigned spread3(unsigned v) {
    return (v & 1u) | ((v & 2u) << 2) | ((v & 4u) << 4);
}

// =====================================================================
// mega kernel: blocks 0..15 run Morton-pruned FPS then convert; all
// consumer blocks = 8 independent warp-PAIR pipelines, 1 centroid/item.
// =====================================================================
__global__ void __launch_bounds__(512, 1) mega_kernel(
    const float* __restrict__ xyz, const float* __restrict__ fea,
    const float* __restrict__ W1, const float* __restrict__ B1,
    const float* __restrict__ W2, const float* __restrict__ B2,
    const float* __restrict__ W3, const float* __restrict__ B3,
    float* __restrict__ out)
{
    extern __shared__ char smp[];
    __shared__ uint2 s_wk[2][16];
    __shared__ int s_item[8];
    __shared__ int s_far0;

    if (blockIdx.x < BATCH) {
        // ================= FPS role (Morton-sorted, box-pruned) =========
        float* sx = (float*)smp;
        float* sy = sx + NPTS;
        float* sz = sy + NPTS;
        int* sidx = (int*)(sz + NPTS);
        int* sspos = sidx + NPTS;
        int* scnt = sspos + NSAMP;
        int* sbase = scnt + 512;

        int b = blockIdx.x, t = threadIdx.x;
        int lane = t & 31, warp = t >> 5;

        float px[16], py[16], pz[16], dist[16];
        int cid[16];
        if (t < 512) scnt[t] = 0;
        __syncthreads();
#pragma unroll
        for (int j = 0; j < 16; j++) {
            int p = t + 512 * j;
            const float* src = xyz + ((size_t)b * NPTS + p) * 3;
            float x = src[0], y = src[1], z = src[2];
            px[j] = x; py[j] = y; pz[j] = z;
            g_p4[b][p] = make_float4(x, y, z,
                __fmaf_rn(z, z, __fmaf_rn(y, y, __fmul_rn(x, x))));
            unsigned ix = min(7, (int)(x * 8.f));
            unsigned iy = min(7, (int)(y * 8.f));
            unsigned iz = min(7, (int)(z * 8.f));
            cid[j] = (int)(spread3(ix) | (spread3(iy) << 1) | (spread3(iz) << 2));
            atomicAdd(&scnt[cid[j]], 1);
        }
        __threadfence();
        __syncthreads();
        if (warp == 0) {
            int c0 = lane * 16, s = 0;
#pragma unroll
            for (int i = 0; i < 16; i++) s += scnt[c0 + i];
            int off = s;
#pragma unroll
            for (int d = 1; d < 32; d <<= 1) {
                int n = __shfl_up_sync(0xffffffffu, off, d);
                if (lane >= d) off += n;
            }
            off -= s;
            int run = off;
#pragma unroll
            for (int i = 0; i < 16; i++) {
                int c = scnt[c0 + i];
                sbase[c0 + i] = run;
                run += c;
            }
        }
        __syncthreads();
#pragma unroll
        for (int j = 0; j < 16; j++) {
            int pos = atomicAdd(&sbase[cid[j]], 1);
            sx[pos] = px[j]; sy[pos] = py[j]; sz[pos] = pz[j];
            sidx[pos] = t + 512 * j;
            if (t == 0 && j == 0) s_far0 = pos;
        }
        __syncthreads();
        float lox = 1e9f, hix = -1e9f, loy = 1e9f, hiy = -1e9f,
              loz = 1e9f, hiz = -1e9f;
#pragma unroll
        for (int j = 0; j < 16; j++) {
            int p = 16 * t + j;
            float x = sx[p], y = sy[p], z = sz[p];
            px[j] = x; py[j] = y; pz[j] = z; dist[j] = 1e10f;
            lox = fminf(lox, x); hix = fmaxf(hix, x);
            loy = fminf(loy, y); hiy = fmaxf(hiy, y);
            loz = fminf(loz, z); hiz = fmaxf(hiz, z);
        }
        float tmax = 1e10f;
        int far_orig = 0, far_spos = s_far0;

        for (int k = 0; k < NSAMP; k++) {
            if (t == 0) { g_fps[b][k] = far_orig; sspos[k] = far_spos; }
            float cx = sx[far_spos], cy = sy[far_spos], cz = sz[far_spos];

            float dxl = fmaxf(fmaxf(__fsub_rn(lox, cx), __fsub_rn(cx, hix)), 0.f);
            float dyl = fmaxf(fmaxf(__fsub_rn(loy, cy), __fsub_rn(cy, hiy)), 0.f);
            float dzl = fmaxf(fmaxf(__fsub_rn(loz, cz), __fsub_rn(cz, hiz)), 0.f);
            float bound = dxl * dxl + dyl * dyl + dzl * dzl;

            if (!(bound * 0.999f > tmax)) {
                float nm = 0.f;
#pragma unroll
                for (int j = 0; j < 16; j++) {
                    float dx = __fsub_rn(px[j], cx);
                    float dy = __fsub_rn(py[j], cy);
                    float dz = __fsub_rn(pz[j], cz);
                    float d = __fmaf_rn(dz, dz, __fmaf_rn(dy, dy, __fmul_rn(dx, dx)));
                    float dm = fminf(dist[j], d);
                    dist[j] = dm;
                    nm = fmaxf(nm, dm);
                }
                tmax = nm;
            }
            unsigned tb = __float_as_uint(tmax);
            unsigned wmax = __reduce_max_sync(0xffffffffu, tb);
            unsigned cand = 0xffffffffu;
            if (tb == wmax) {
#pragma unroll
                for (int j = 0; j < 16; j++)
                    if (__float_as_uint(dist[j]) == wmax) {
                        int sp = 16 * t + j;
                        unsigned key = ((unsigned)sidx[sp] << 13) | (unsigned)sp;
                        cand = min(cand, key);
                    }
            }
            unsigned widx = __reduce_min_sync(0xffffffffu, cand);
            if (lane == 0) s_wk[k & 1][warp] = make_uint2(wmax, widx);
            __syncthreads();
            uint2 v = (lane < 16) ? s_wk[k & 1][lane] : make_uint2(0u, 0xffffffffu);
            unsigned m2 = __reduce_max_sync(0xffffffffu, v.x);
            unsigned c2 = (v.x == m2) ? v.y : 0xffffffffu;
            c2 = __reduce_min_sync(0xffffffffu, c2);
            far_orig = (int)(c2 >> 13);
            far_spos = (int)(c2 & 8191u);

            if (t == 0 && ((k + 1) & 7) == 0) {
                __threadfence();
                *(volatile int*)&g_prog[b] = k + 1;
            }
        }
        __syncthreads();
        for (int k = t; k < NSAMP; k += 512) {
            int sp = sspos[k];
            size_t o = ((size_t)b * NSAMP + k) * 3;
            out[o + 0] = sx[sp];
            out[o + 1] = sy[sp];
            out[o + 2] = sz[sp];
        }
        __syncthreads();
        // fall through: convert to consumer
    }

    // ========== persistent consumers: 8 independent warp-pair pipelines ====
    uint32_t sb = smem_u32(smp);
    int tid = threadIdx.x, lane = tid & 31;
    int wid = tid >> 5;
    int pair = wid >> 1;
    int nhalf = wid & 1;
    int ptid = tid & 63;                 // id within pair

    char* aBase = smp + pair * PAIR_A;
    uint32_t aB = sb + pair * PAIR_A;
    int barid = 1 + pair;
#define PBAR() asm volatile("bar.sync %0, 64;" :: "r"(barid) : "memory")

    for (;;) {
        if (ptid == 0) {
            int v = atomicAdd(&g_qhead, 1);
            if (v < NITEM) {
                int bb = v & 15, need = (v >> 4) + 1;
                while (*(volatile int*)&g_prog[bb] < need) __nanosleep(128);
                __threadfence();
            }
            s_item[pair] = v;
        }
        PBAR();
        int v = s_item[pair];
        if (v >= NITEM) break;
        int b = v & 15;
        int s = v >> 4;
        int far = __ldcg(&g_fps[b][s]);

        // ballq by even warp of the pair (next-chunk LDG prefetch)
        if (nhalf == 0) {
            float4 c4 = __ldg(&g_p4[b][far]);
            float ax = c4.x, ay = c4.y, az = c4.z, sa = c4.w;
            const float RR = 0.04f;
            int filled = 0;
            float4 p = __ldg(&g_p4[b][lane]);
            for (int base = 0; base < NPTS; base += 32) {
                float4 cur = p;
                if (base + 32 < NPTS) p = __ldg(&g_p4[b][base + 32 + lane]);
                float dot = __fmaf_rn(az, cur.z,
                              __fmaf_rn(ay, cur.y, __fmul_rn(ax, cur.x)));
                float sq = __fsub_rn(__fadd_rn(sa, cur.w), __fmul_rn(2.0f, dot));
                bool inr = !(sq > RR);
                unsigned m = __ballot_sync(0xffffffffu, inr);
                int pos = filled + __popc(m & ((1u << lane) - 1u));
                if (inr && pos < NGRP) g_grp[b][s][pos] = base + lane;
                filled += __popc(m);
                if (filled >= NGRP) break;
            }
            if (filled < NGRP) {
                __syncwarp();
                int first = g_grp[b][s][0];
                int j = filled + lane;
                if (j < NGRP) g_grp[b][s][j] = first;
            }
        }
        PBAR();

        // gather: 64 threads, 2 per row (half 0: cols 0..39; half 1: cols 40..79)
        {
            int row = ptid >> 1;
            int half = ptid & 1;
            int idx = g_grp[b][s][row];
            const float4* fr = (const float4*)(fea + ((size_t)b * NPTS + idx) * FDIM);
            float f[40];
            if (half == 0) {
                float4 pc = __ldg(&g_p4[b][far]);
                float4 pi = __ldg(&g_p4[b][idx]);
                f[0] = pi.x - pc.x; f[1] = pi.y - pc.y; f[2] = pi.z - pc.z;
#pragma unroll
                for (int q = 0; q < 10; q++) {
                    float4 vv = __ldg(fr + q);
                    if (3 + 4 * q     < 40) f[3 + 4 * q]     = vv.x;
                    if (3 + 4 * q + 1 < 40) f[3 + 4 * q + 1] = vv.y;
                    if (3 + 4 * q + 2 < 40) f[3 + 4 * q + 2] = vv.z;
                    if (3 + 4 * q + 3 < 40) f[3 + 4 * q + 3] = vv.w;
                }
#pragma unroll
                for (int q = 0; q < 20; q++)
                    storeA(aBase, row, 2 * q, f[2 * q], f[2 * q + 1]);
            } else {
                float4 v9 = __ldg(fr + 9);
                f[0] = v9.y; f[1] = v9.z; f[2] = v9.w;
#pragma unroll
                for (int q = 0; q < 6; q++) {
                    float4 vv = __ldg(fr + 10 + q);
                    f[3 + 4 * q]     = vv.x;
                    f[3 + 4 * q + 1] = vv.y;
                    f[3 + 4 * q + 2] = vv.z;
                    f[3 + 4 * q + 3] = vv.w;
                }
#pragma unroll
                for (int i = 27; i < 40; i++) f[i] = 0.f;
#pragma unroll
                for (int q = 0; q < 20; q++)
                    storeA(aBase, row, 40 + 2 * q, f[2 * q], f[2 * q + 1]);
            }
        }
        PBAR();

        // L1: [32x80] @ [80x64]
        {
            float acc[2][4][4];
            warp_gemm_ldg<4, 5>(aB, g_W1f, nhalf * 4, 5, acc);
            PBAR();
            epi_store<4>(aBase, nhalf * 32, B1, acc);
            PBAR();
        }
        // L2: [32x64] @ [64x128]
        {
            float acc[2][8][4];
            warp_gemm_ldg<8, 4>(aB, g_W2f, nhalf * 8, 4, acc);
            PBAR();
            epi_store<8>(aBase, nhalf * 64, B2, acc);
            PBAR();
        }
        // L3: [32x128] @ [128x256] as 2 barrier-free NBLK=8 sub-GEMMs + maxpool
        size_t obase = (size_t)BATCH * NSAMP * 3 +
                       ((size_t)(b * NSAMP + s)) * 256;
        {
            float acc[2][8][4];
#pragma unroll
            for (int ci = 0; ci < 2; ci++) {
                warp_gemm_ldg<8, 8>(aB, g_W3f, ci * 16 + nhalf * 8, 8, acc);
                epi_max<8>(ci * 128 + nhalf * 64, B3, out, obase, acc);
            }
        }
    }
#undef PBAR
}

// ---------------- launcher ----------------
extern "C" void kernel_launch(void* const* d_in, const int* in_sizes, int n_in,
                              void* d_out, int out_size) {
    (void)in_sizes; (void)n_in; (void)out_size;
    const float* xyz = (const float*)d_in[0];
    const float* fea = (const float*)d_in[1];
    const float* W1  = (const float*)d_in[2];
    const float* B1  = (const float*)d_in[3];
    const float* W2  = (const float*)d_in[4];
    const float* B2  = (const float*)d_in[5];
    const float* W3  = (const float*)d_in[6];
    const float* B3  = (const float*)d_in[7];
    float* out = (float*)d_out;

    cudaFuncSetAttribute(mega_kernel, cudaFuncAttributeMaxDynamicSharedMemorySize,
                         SMEM_TOT);

    init_kernel<<<200, 256>>>(W1, W2, W3);
    int grid = BATCH + 136;
    mega_kernel<<<grid, 512, SMEM_TOT>>>(xyz, fea, W1, B1, W2, B2, W3, B3, out);
}